// round 8
// baseline (speedup 1.0000x reference)
#include <cuda_runtime.h>
#include <cuda_fp16.h>
#include <math.h>

// SlowROIPool R7: R6 + occupancy push. Grid doubled via ROI half-segments
// (each (image, channel-pair) processed by 2 blocks), registers capped to 42
// via __launch_bounds__(256,6) -> 6 blocks/SM, ~75% occ ceiling (was 39%).
// Reg diet: x-bin bounds loaded only after pass 1.
// images: [8,128,56,56] f32, rois: [512,4] f32, roi_idx: [512] i32,
// out: [512,128,7,7] f32.

#define OUT_D 7
#define NWARP 8
#define PSW 48                      // plane row stride in half2 words (96 halves)
#define PPW (56 * PSW + 16)         // per-plane words; +16 keeps PPW % 32 == 16
                                    // so ch0/ch1 half-warps use disjoint banks

__device__ int        g_meta[512];  // roi | cp0<<16 | narrow<<24
__device__ ulonglong2 g_ybin[512];  // {ysP, nP}: byte i = ys / row-count of y-bin i
__device__ ulonglong2 g_xbin[512];  // {xsP, xeP}: byte j = half-index bounds of x-bin j
__device__ int        g_start[9];   // per-image segment starts

__global__ void prep_kernel(const float* __restrict__ rois,
                            const int*   __restrict__ roi_idx)
{
    __shared__ int cnt[8];
    __shared__ int base[8];
    const int tid = threadIdx.x;        // 512 threads, one block
    if (tid < 8) cnt[tid] = 0;
    __syncthreads();
    const int img = roi_idx[tid];
    atomicAdd(&cnt[img], 1);
    __syncthreads();
    if (tid == 0) {
        int acc = 0;
        for (int i = 0; i < 8; i++) { base[i] = acc; g_start[i] = acc; acc += cnt[i]; }
        g_start[8] = acc;
    }
    __syncthreads();
    if (tid < 8) cnt[tid] = 0;
    __syncthreads();

    const float4 box = reinterpret_cast<const float4*>(rois)[tid];
    // Match jnp: fp32 floor/ceil then int cast.
    const int x1 = (int)floorf(box.x * 56.0f);
    const int y1 = (int)floorf(box.y * 56.0f);
    const int x2 = (int)ceilf (box.z * 56.0f);
    const int y2 = (int)ceilf (box.w * 56.0f);
    const int Lx = x2 - x1, Ly = y2 - y1;
    const int frac = x1 & 1;

    unsigned long long ysP = 0, nP = 0, xsP = 0, xeP = 0;
    for (int j = 0; j < OUT_D; j++) {
        const int ys = y1 + (j * Ly) / 7;
        const int ye = y1 + ((j + 1) * Ly + 6) / 7;     // ceil div, ye > ys
        ysP |= (unsigned long long)ys << (8 * j);
        nP  |= (unsigned long long)(ye - ys) << (8 * j);
        const int xs = (j * Lx) / 7 + frac;             // half-index in colmax
        const int xe = ((j + 1) * Lx + 6) / 7 + frac;
        xsP |= (unsigned long long)xs << (8 * j);
        xeP |= (unsigned long long)xe << (8 * j);
    }
    const int narrow = (frac + Lx) <= 32;
    const int cp0 = (x1 >> 1);                          // first half2 word covered

    const int pos = base[img] + atomicAdd(&cnt[img], 1);
    g_meta[pos] = tid | (cp0 << 16) | (narrow << 24);
    g_ybin[pos] = make_ulonglong2(ysP, nP);
    g_xbin[pos] = make_ulonglong2(xsP, xeP);
}

__device__ __forceinline__ int bget(unsigned long long p, int i) {
    return (int)((p >> (8 * i)) & 0xFF);
}

__global__ __launch_bounds__(256, 6)
void roipool_kernel(const float* __restrict__ images,
                    float*       __restrict__ out)
{
    __shared__ __half2 planeW[2 * PPW];                  // 21.1 KB (2 channels)
    __shared__ __half2 colmax[2][NWARP][OUT_D][32];      // 14.0 KB

    const int blk  = blockIdx.x;                         // (b*64 + cpair)*2 + half
    const int half = blk & 1;
    const int bc   = blk >> 1;
    const int b    = bc >> 6;
    const int c0   = (bc & 63) * 2;
    // two consecutive channel planes = contiguous 6272 floats
    const float4* src = reinterpret_cast<const float4*>(images + (size_t)(b * 128 + c0) * 3136);

    const int tid  = threadIdx.x;
    const int warp = tid >> 5;
    const int lane = tid & 31;

    // Stage both planes as fp16 (rows padded to 48 words = 96 halves).
    for (int j = tid; j < 1568; j += 256) {
        float4 v = src[j];
        const int ch = (j >= 784);
        const int jj = j - ch * 784;
        const int y  = jj / 14;
        const int w  = ch * PPW + y * PSW + (jj - y * 14) * 2;
        planeW[w]     = __floats2half2_rn(v.x, v.y);
        planeW[w + 1] = __floats2half2_rn(v.z, v.w);
    }
    const int s = g_start[b];
    const int e = g_start[b + 1];
    __syncthreads();

    // ROI half-segment: this block handles k = s + half*8 + warp, step 16.
    for (int k = s + half * NWARP + warp; k < e; k += 2 * NWARP) {
        const int meta = g_meta[k];
        const ulonglong2 yb = g_ybin[k];
        const int cp0    = (meta >> 16) & 0xFF;
        const int narrow =  meta >> 24;

        if (narrow) {
            // Half-warp per channel: lanes 0-15 ch0, 16-31 ch1.
            const int q  = lane & 15;
            const int ch = lane >> 4;
            const __half2* pbase = planeW + ch * PPW + cp0 + q;
            #pragma unroll
            for (int i = 0; i < OUT_D; i++) {
                const int ys = bget(yb.x, i);
                const int n  = bget(yb.y, i);
                const __half2* ptr = pbase + ys * PSW;
                __half2 m = ptr[0];                      // peel (bin non-empty)
                int rem = n - 1;
                ptr += PSW;
                while (rem >= 2) {                       // unroll 2
                    __half2 a = ptr[0];
                    __half2 d = ptr[PSW];
                    m = __hmax2(__hmax2(m, a), d);
                    ptr += 2 * PSW;
                    rem -= 2;
                }
                if (rem) m = __hmax2(m, ptr[0]);
                colmax[ch][warp][i][q] = m;
            }
        } else {
            // 32 lanes cover up to 64 halves; both channels per lane (2x ILP).
            const __half2* pbase = planeW + cp0 + lane;
            #pragma unroll
            for (int i = 0; i < OUT_D; i++) {
                const int ys = bget(yb.x, i);
                const int n  = bget(yb.y, i);
                const __half2* ptr = pbase + ys * PSW;
                __half2 m0 = ptr[0];
                __half2 m1 = ptr[PPW];
                int rem = n - 1;
                ptr += PSW;
                while (rem >= 2) {                       // unroll 2
                    __half2 a0 = ptr[0],   a1 = ptr[PPW];
                    __half2 d0 = ptr[PSW], d1 = ptr[PSW + PPW];
                    m0 = __hmax2(__hmax2(m0, a0), d0);
                    m1 = __hmax2(__hmax2(m1, a1), d1);
                    ptr += 2 * PSW;
                    rem -= 2;
                }
                if (rem) {
                    m0 = __hmax2(m0, ptr[0]);
                    m1 = __hmax2(m1, ptr[PPW]);
                }
                colmax[0][warp][i][lane] = m0;
                colmax[1][warp][i][lane] = m1;
            }
        }
        __syncwarp();

        // ---- Pass 2: 49 outputs x 2 channels; shared index math ----
        // xb loaded only here (keeps pass-1 register pressure low).
        const ulonglong2 xb = g_xbin[k];
        const int r = meta & 0xFFFF;
        float* outr = out + ((size_t)r * 128 + c0) * (OUT_D * OUT_D);
        #pragma unroll
        for (int bs = 0; bs < 64; bs += 32) {
            const int o = bs + lane;
            if (o < OUT_D * OUT_D) {
                const int i  = (o * 37) >> 8;            // o/7 for o<49
                const int j  = o - i * 7;
                const int xs = bget(xb.x, j);
                const int xe = bget(xb.y, j);
                const __half* cA = reinterpret_cast<const __half*>(&colmax[0][warp][i][0]);
                const __half* cB = reinterpret_cast<const __half*>(&colmax[1][warp][i][0]);
                __half m0 = cA[xs];
                __half m1 = cB[xs];
                for (int x = xs + 1; x < xe; x++) {
                    m0 = __hmax(m0, cA[x]);
                    m1 = __hmax(m1, cB[x]);
                }
                outr[o]                 = __half2float(m0);
                outr[o + OUT_D * OUT_D] = __half2float(m1);
            }
        }
        __syncwarp();   // protect colmax before next ROI's pass 1
    }
}

extern "C" void kernel_launch(void* const* d_in, const int* in_sizes, int n_in,
                              void* d_out, int out_size)
{
    const float* images  = (const float*)d_in[0];   // [8,128,56,56]
    const float* rois    = (const float*)d_in[1];   // [512,4]
    const int*   roi_idx = (const int*)  d_in[2];   // [512]
    float*       out     = (float*)d_out;           // [512,128,7,7]

    prep_kernel<<<1, 512>>>(rois, roi_idx);
    roipool_kernel<<<8 * 64 * 2, 256>>>(images, out);
}

// round 10
// speedup vs baseline: 1.0639x; 1.0639x over previous
#include <cuda_runtime.h>
#include <cuda_fp16.h>
#include <math.h>

// SlowROIPool R10: R9 retry with DYNAMIC shared memory (static smem capped at
// 48KB; we need 50.3KB). Grid 512, one block per (image, channel-pair), plane
// staged once, 512-thread blocks = 16 warps -> ~55 warps/SM (occupancy A/B
// against R6's 27.7 at identical instruction count).
// images: [8,128,56,56] f32, rois: [512,4] f32, roi_idx: [512] i32,
// out: [512,128,7,7] f32.

#define OUT_D 7
#define NWARP 16
#define NTHREADS 512
#define PSW 48                      // plane row stride in half2 words (96 halves)
#define PPW (56 * PSW + 16)         // per-plane words; +16 keeps PPW % 32 == 16
                                    // so ch0/ch1 half-warps use disjoint banks
// dynamic smem layout (in half2 words):
//   [0, 2*PPW)                      : two channel planes
//   [2*PPW, 2*PPW + 2*NWARP*7*32)   : colmax[ch][warp][bin][32]
#define CM_BASE (2 * PPW)
#define SMEM_WORDS (CM_BASE + 2 * NWARP * OUT_D * 32)
#define SMEM_BYTES (SMEM_WORDS * 4)          // 50304 B

__device__ int        g_meta[512];  // roi | cp0<<16 | narrow<<24
__device__ ulonglong2 g_ybin[512];  // {ysP, nP}: byte i = ys / row-count of y-bin i
__device__ ulonglong2 g_xbin[512];  // {xsP, xeP}: byte j = half-index bounds of x-bin j
__device__ int        g_start[9];   // per-image segment starts

__global__ void prep_kernel(const float* __restrict__ rois,
                            const int*   __restrict__ roi_idx)
{
    __shared__ int cnt[8];
    __shared__ int base[8];
    const int tid = threadIdx.x;        // 512 threads, one block
    if (tid < 8) cnt[tid] = 0;
    __syncthreads();
    const int img = roi_idx[tid];
    atomicAdd(&cnt[img], 1);
    __syncthreads();
    if (tid == 0) {
        int acc = 0;
        for (int i = 0; i < 8; i++) { base[i] = acc; g_start[i] = acc; acc += cnt[i]; }
        g_start[8] = acc;
    }
    __syncthreads();
    if (tid < 8) cnt[tid] = 0;
    __syncthreads();

    const float4 box = reinterpret_cast<const float4*>(rois)[tid];
    // Match jnp: fp32 floor/ceil then int cast.
    const int x1 = (int)floorf(box.x * 56.0f);
    const int y1 = (int)floorf(box.y * 56.0f);
    const int x2 = (int)ceilf (box.z * 56.0f);
    const int y2 = (int)ceilf (box.w * 56.0f);
    const int Lx = x2 - x1, Ly = y2 - y1;
    const int frac = x1 & 1;

    unsigned long long ysP = 0, nP = 0, xsP = 0, xeP = 0;
    for (int j = 0; j < OUT_D; j++) {
        const int ys = y1 + (j * Ly) / 7;
        const int ye = y1 + ((j + 1) * Ly + 6) / 7;     // ceil div, ye > ys
        ysP |= (unsigned long long)ys << (8 * j);
        nP  |= (unsigned long long)(ye - ys) << (8 * j);
        const int xs = (j * Lx) / 7 + frac;             // half-index in colmax
        const int xe = ((j + 1) * Lx + 6) / 7 + frac;
        xsP |= (unsigned long long)xs << (8 * j);
        xeP |= (unsigned long long)xe << (8 * j);
    }
    const int narrow = (frac + Lx) <= 32;
    const int cp0 = (x1 >> 1);                          // first half2 word covered

    const int pos = base[img] + atomicAdd(&cnt[img], 1);
    g_meta[pos] = tid | (cp0 << 16) | (narrow << 24);
    g_ybin[pos] = make_ulonglong2(ysP, nP);
    g_xbin[pos] = make_ulonglong2(xsP, xeP);
}

__device__ __forceinline__ int bget(unsigned long long p, int i) {
    return (int)((p >> (8 * i)) & 0xFF);
}

__global__ __launch_bounds__(NTHREADS, 3)
void roipool_kernel(const float* __restrict__ images,
                    float*       __restrict__ out)
{
    extern __shared__ __half2 smemW[];
    __half2* planeW = smemW;                             // 2 planes

    const int bc = blockIdx.x;                           // b*64 + cpair
    const int b  = bc >> 6;
    const int c0 = (bc & 63) * 2;
    // two consecutive channel planes = contiguous 6272 floats
    const float4* src = reinterpret_cast<const float4*>(images + (size_t)(b * 128 + c0) * 3136);

    const int tid  = threadIdx.x;
    const int warp = tid >> 5;
    const int lane = tid & 31;

    // Stage both planes as fp16 (rows padded to 48 words = 96 halves).
    for (int j = tid; j < 1568; j += NTHREADS) {
        float4 v = src[j];
        const int ch = (j >= 784);
        const int jj = j - ch * 784;
        const int y  = jj / 14;
        const int w  = ch * PPW + y * PSW + (jj - y * 14) * 2;
        planeW[w]     = __floats2half2_rn(v.x, v.y);
        planeW[w + 1] = __floats2half2_rn(v.z, v.w);
    }
    const int s = g_start[b];
    const int e = g_start[b + 1];
    // per-warp colmax scratch: [ch][bin][32] words
    __half2* cmw = smemW + CM_BASE + warp * (OUT_D * 32);
    __half2* cmw1 = cmw + NWARP * (OUT_D * 32);          // channel-1 block
    __syncthreads();

    for (int k = s + warp; k < e; k += NWARP) {
        const int meta = g_meta[k];
        const ulonglong2 yb = g_ybin[k];
        const int cp0    = (meta >> 16) & 0xFF;
        const int narrow =  meta >> 24;

        if (narrow) {
            // Half-warp per channel: lanes 0-15 ch0, 16-31 ch1.
            const int q  = lane & 15;
            const int ch = lane >> 4;
            const __half2* pbase = planeW + ch * PPW + cp0 + q;
            __half2* cmc = ch ? cmw1 : cmw;
            #pragma unroll
            for (int i = 0; i < OUT_D; i++) {
                const int ys = bget(yb.x, i);
                const int n  = bget(yb.y, i);
                const __half2* ptr = pbase + ys * PSW;
                __half2 m = ptr[0];                      // peel (bin non-empty)
                int rem = n - 1;
                ptr += PSW;
                while (rem >= 2) {                       // unroll 2
                    __half2 a = ptr[0];
                    __half2 d = ptr[PSW];
                    m = __hmax2(__hmax2(m, a), d);
                    ptr += 2 * PSW;
                    rem -= 2;
                }
                if (rem) m = __hmax2(m, ptr[0]);
                cmc[i * 32 + q] = m;
            }
        } else {
            // 32 lanes cover up to 64 halves; both channels per lane (2x ILP).
            const __half2* pbase = planeW + cp0 + lane;
            #pragma unroll
            for (int i = 0; i < OUT_D; i++) {
                const int ys = bget(yb.x, i);
                const int n  = bget(yb.y, i);
                const __half2* ptr = pbase + ys * PSW;
                __half2 m0 = ptr[0];
                __half2 m1 = ptr[PPW];
                int rem = n - 1;
                ptr += PSW;
                while (rem >= 2) {                       // unroll 2
                    __half2 a0 = ptr[0],   a1 = ptr[PPW];
                    __half2 d0 = ptr[PSW], d1 = ptr[PSW + PPW];
                    m0 = __hmax2(__hmax2(m0, a0), d0);
                    m1 = __hmax2(__hmax2(m1, a1), d1);
                    ptr += 2 * PSW;
                    rem -= 2;
                }
                if (rem) {
                    m0 = __hmax2(m0, ptr[0]);
                    m1 = __hmax2(m1, ptr[PPW]);
                }
                cmw [i * 32 + lane] = m0;
                cmw1[i * 32 + lane] = m1;
            }
        }
        __syncwarp();

        // ---- Pass 2: 49 outputs x 2 channels; shared index math ----
        // xb loaded only here (keeps pass-1 register pressure low).
        const ulonglong2 xb = g_xbin[k];
        const int r = meta & 0xFFFF;
        float* outr = out + ((size_t)r * 128 + c0) * (OUT_D * OUT_D);
        #pragma unroll
        for (int bs = 0; bs < 64; bs += 32) {
            const int o = bs + lane;
            if (o < OUT_D * OUT_D) {
                const int i  = (o * 37) >> 8;            // o/7 for o<49
                const int j  = o - i * 7;
                const int xs = bget(xb.x, j);
                const int xe = bget(xb.y, j);
                const __half* cA = reinterpret_cast<const __half*>(cmw  + i * 32);
                const __half* cB = reinterpret_cast<const __half*>(cmw1 + i * 32);
                __half m0 = cA[xs];
                __half m1 = cB[xs];
                for (int x = xs + 1; x < xe; x++) {
                    m0 = __hmax(m0, cA[x]);
                    m1 = __hmax(m1, cB[x]);
                }
                outr[o]                 = __half2float(m0);
                outr[o + OUT_D * OUT_D] = __half2float(m1);
            }
        }
        __syncwarp();   // protect colmax before next ROI's pass 1
    }
}

extern "C" void kernel_launch(void* const* d_in, const int* in_sizes, int n_in,
                              void* d_out, int out_size)
{
    const float* images  = (const float*)d_in[0];   // [8,128,56,56]
    const float* rois    = (const float*)d_in[1];   // [512,4]
    const int*   roi_idx = (const int*)  d_in[2];   // [512]
    float*       out     = (float*)d_out;           // [512,128,7,7]

    // Opt into >48KB dynamic shared memory (deterministic, not an allocation,
    // not stream work -> graph-capture safe).
    cudaFuncSetAttribute(roipool_kernel,
                         cudaFuncAttributeMaxDynamicSharedMemorySize, SMEM_BYTES);

    prep_kernel<<<1, 512>>>(rois, roi_idx);
    roipool_kernel<<<8 * 64, NTHREADS, SMEM_BYTES>>>(images, out);
}

// round 12
// speedup vs baseline: 1.0759x; 1.0113x over previous
#include <cuda_runtime.h>
#include <cuda_fp16.h>
#include <math.h>

// SlowROIPool R11: R6 config (grid 512, 256 thr, 8 warps) + LDS.64
// vectorization: each lane loads an aligned __half2 pair (4 halves) per LDS,
// halving shared-memory instruction count. Wide: 16 lanes/channel cover 64
// halves. Narrow: quarter-warps (8 lanes x 2 row-parities x 2 channels),
// parity merge via 2 shfl per bin. Base 4-half-aligned (cp0q = x1>>2,
// frac3 = x1&3 folded into precomputed x-bin indices).
// images: [8,128,56,56] f32, rois: [512,4] f32, roi_idx: [512] i32,
// out: [512,128,7,7] f32.

#define OUT_D 7
#define NWARP 8
#define PSW  48                 // plane row stride in half2 words (96 halves)
#define PSW2 24                 // row stride in H4 (8-byte) units
#define PPW  (56 * PSW + 16)    // per-plane words; PPW % 32 == 16 -> ch1 on
#define PPW2 (PPW / 2)          // complementary bank half

__device__ int        g_meta[512];  // roi | cp0q<<16 | narrow<<24
__device__ ulonglong2 g_ybin[512];  // {ysP, nP}: byte i = ys / row-count of y-bin i
__device__ ulonglong2 g_xbin[512];  // {xsP, xeP}: byte j = half-index bounds (frac3-based)
__device__ int        g_start[9];   // per-image segment starts

__global__ void prep_kernel(const float* __restrict__ rois,
                            const int*   __restrict__ roi_idx)
{
    __shared__ int cnt[8];
    __shared__ int base[8];
    const int tid = threadIdx.x;        // 512 threads, one block
    if (tid < 8) cnt[tid] = 0;
    __syncthreads();
    const int img = roi_idx[tid];
    atomicAdd(&cnt[img], 1);
    __syncthreads();
    if (tid == 0) {
        int acc = 0;
        for (int i = 0; i < 8; i++) { base[i] = acc; g_start[i] = acc; acc += cnt[i]; }
        g_start[8] = acc;
    }
    __syncthreads();
    if (tid < 8) cnt[tid] = 0;
    __syncthreads();

    const float4 box = reinterpret_cast<const float4*>(rois)[tid];
    // Match jnp: fp32 floor/ceil then int cast.
    const int x1 = (int)floorf(box.x * 56.0f);
    const int y1 = (int)floorf(box.y * 56.0f);
    const int x2 = (int)ceilf (box.z * 56.0f);
    const int y2 = (int)ceilf (box.w * 56.0f);
    const int Lx = x2 - x1, Ly = y2 - y1;
    const int frac3 = x1 & 3;           // offset from 4-half-aligned base
    const int cp0q  = x1 >> 2;          // H4-unit base within row (<= 6)

    unsigned long long ysP = 0, nP = 0, xsP = 0, xeP = 0;
    for (int j = 0; j < OUT_D; j++) {
        const int ys = y1 + (j * Ly) / 7;
        const int ye = y1 + ((j + 1) * Ly + 6) / 7;     // ceil div, ye > ys
        ysP |= (unsigned long long)ys << (8 * j);
        nP  |= (unsigned long long)(ye - ys) << (8 * j);
        const int xs = (j * Lx) / 7 + frac3;            // half-index in colmax
        const int xe = ((j + 1) * Lx + 6) / 7 + frac3;  // <= 59 < 64
        xsP |= (unsigned long long)xs << (8 * j);
        xeP |= (unsigned long long)xe << (8 * j);
    }
    const int narrow = (frac3 + Lx) <= 32;

    const int pos = base[img] + atomicAdd(&cnt[img], 1);
    g_meta[pos] = tid | (cp0q << 16) | (narrow << 24);
    g_ybin[pos] = make_ulonglong2(ysP, nP);
    g_xbin[pos] = make_ulonglong2(xsP, xeP);
}

__device__ __forceinline__ int bget(unsigned long long p, int i) {
    return (int)((p >> (8 * i)) & 0xFF);
}

struct __align__(8) H4 { __half2 a, b; };

__device__ __forceinline__ H4 h4max(H4 x, H4 y) {
    x.a = __hmax2(x.a, y.a);
    x.b = __hmax2(x.b, y.b);
    return x;
}
__device__ __forceinline__ unsigned h2u(__half2 v) { return *reinterpret_cast<unsigned*>(&v); }
__device__ __forceinline__ __half2 u2h(unsigned v) { return *reinterpret_cast<__half2*>(&v); }

__global__ __launch_bounds__(256, 6)
void roipool_kernel(const float* __restrict__ images,
                    float*       __restrict__ out)
{
    __shared__ __align__(16) __half2 planeW[2 * PPW];               // 21632 B
    // colmax: ch0 block [0,1792), pad 16, ch1 block (+16-bank offset)
    __shared__ __align__(16) __half2 colmaxA[2 * NWARP * OUT_D * 32 + 16];  // 14400 B

    const int bc = blockIdx.x;                           // b*64 + cpair
    const int b  = bc >> 6;
    const int c0 = (bc & 63) * 2;
    const float4* src = reinterpret_cast<const float4*>(images + (size_t)(b * 128 + c0) * 3136);

    const int tid  = threadIdx.x;
    const int warp = tid >> 5;
    const int lane = tid & 31;

    // Stage both planes as fp16 (rows padded to 48 words = 96 halves).
    for (int j = tid; j < 1568; j += 256) {
        float4 v = src[j];
        const int ch = (j >= 784);
        const int jj = j - ch * 784;
        const int y  = jj / 14;
        const int w  = ch * PPW + y * PSW + (jj - y * 14) * 2;
        planeW[w]     = __floats2half2_rn(v.x, v.y);
        planeW[w + 1] = __floats2half2_rn(v.z, v.w);
    }
    const int s = g_start[b];
    const int e = g_start[b + 1];
    const H4* pl = reinterpret_cast<const H4*>(planeW);
    __half2* cmw  = colmaxA + warp * (OUT_D * 32);
    __half2* cmw1 = colmaxA + NWARP * (OUT_D * 32) + 16 + warp * (OUT_D * 32);
    __syncthreads();

    for (int k = s + warp; k < e; k += NWARP) {
        const int meta = g_meta[k];
        const ulonglong2 yb = g_ybin[k];
        const int cp0q   = (meta >> 16) & 0xFF;
        const int narrow =  meta >> 24;

        if (narrow) {
            // quarter-warps: q = H4 column, p = row parity, ch = channel
            const int q  = lane & 7;
            const int p  = (lane >> 3) & 1;
            const int ch = lane >> 4;
            const H4* base = pl + ch * PPW2 + cp0q + q;
            __half2* cmc = ch ? cmw1 : cmw;
            #pragma unroll
            for (int i = 0; i < OUT_D; i++) {
                const int ys = bget(yb.x, i);
                const int n  = bget(yb.y, i);
                const int np = (n + 1 - p) >> 1;          // parity-p row count
                const int r0 = np ? (ys + p) : ys;        // np==0: re-read ys
                const H4* ptr = base + r0 * PSW2;
                H4 m = ptr[0];
                int rem = np ? (np - 1) : 0;
                ptr += 2 * PSW2;
                while (rem >= 2) {                        // unroll 2 (4 plane rows)
                    m = h4max(h4max(m, ptr[0]), ptr[2 * PSW2]);
                    ptr += 4 * PSW2;
                    rem -= 2;
                }
                if (rem) m = h4max(m, ptr[0]);
                // merge the two row parities
                const unsigned ax = __shfl_xor_sync(0xFFFFFFFFu, h2u(m.a), 8);
                const unsigned bx = __shfl_xor_sync(0xFFFFFFFFu, h2u(m.b), 8);
                m.a = __hmax2(m.a, u2h(ax));
                m.b = __hmax2(m.b, u2h(bx));
                if (p == 0) reinterpret_cast<H4*>(cmc + i * 32)[q] = m;
            }
        } else {
            // 16 lanes per channel cover 64 halves, 1 row per LDS.64.
            const int q  = lane & 15;
            const int ch = lane >> 4;
            const H4* base = pl + ch * PPW2 + cp0q + q;
            __half2* cmc = ch ? cmw1 : cmw;
            #pragma unroll
            for (int i = 0; i < OUT_D; i++) {
                const int ys = bget(yb.x, i);
                const int n  = bget(yb.y, i);
                const H4* ptr = base + ys * PSW2;
                H4 m = ptr[0];                            // peel (bin non-empty)
                int rem = n - 1;
                ptr += PSW2;
                while (rem >= 2) {                        // unroll 2
                    m = h4max(h4max(m, ptr[0]), ptr[PSW2]);
                    ptr += 2 * PSW2;
                    rem -= 2;
                }
                if (rem) m = h4max(m, ptr[0]);
                reinterpret_cast<H4*>(cmc + i * 32)[q] = m;
            }
        }
        __syncwarp();

        // ---- Pass 2: 49 outputs x 2 channels; shared index math ----
        const ulonglong2 xb = g_xbin[k];
        const int r = meta & 0xFFFF;
        float* outr = out + ((size_t)r * 128 + c0) * (OUT_D * OUT_D);
        #pragma unroll
        for (int bs = 0; bs < 64; bs += 32) {
            const int o = bs + lane;
            if (o < OUT_D * OUT_D) {
                const int i  = (o * 37) >> 8;             // o/7 for o<49
                const int j  = o - i * 7;
                const int xs = bget(xb.x, j);
                const int xe = bget(xb.y, j);
                const __half* cA = reinterpret_cast<const __half*>(cmw  + i * 32);
                const __half* cB = reinterpret_cast<const __half*>(cmw1 + i * 32);
                __half m0 = cA[xs];
                __half m1 = cB[xs];
                for (int x = xs + 1; x < xe; x++) {
                    m0 = __hmax(m0, cA[x]);
                    m1 = __hmax(m1, cB[x]);
                }
                outr[o]                 = __half2float(m0);
                outr[o + OUT_D * OUT_D] = __half2float(m1);
            }
        }
        __syncwarp();   // protect colmax before next ROI's pass 1
    }
}

extern "C" void kernel_launch(void* const* d_in, const int* in_sizes, int n_in,
                              void* d_out, int out_size)
{
    const float* images  = (const float*)d_in[0];   // [8,128,56,56]
    const float* rois    = (const float*)d_in[1];   // [512,4]
    const int*   roi_idx = (const int*)  d_in[2];   // [512]
    float*       out     = (float*)d_out;           // [512,128,7,7]

    prep_kernel<<<1, 512>>>(rois, roi_idx);
    roipool_kernel<<<8 * 64, 256>>>(images, out);
}

// round 14
// speedup vs baseline: 1.2241x; 1.1378x over previous
#include <cuda_runtime.h>
#include <cuda_fp16.h>
#include <math.h>

// SlowROIPool R14: R13 with the convert-kernel grid fixed (needs 802,816
// float4 threads = 3136 blocks x 256; R13 launched 784 blocks and converted
// only 1/4 of the planes -> rel_err 0.88).
//  - convert_kernel: images fp32 -> padded fp16 global planes (rows padded
//    56->64 halves). Done ONCE; pooling blocks no longer stage/convert.
//  - roipool_kernel reads planes via __ldg (L1-cached; each block touches
//    ~14KB). No block-wide syncs, no SMEM plane.
//  - Grid 1024 = (image, cpair, roi-half): 7 blocks/SM, single wave.
//  - prep counting-sorts each image's ROIs by descending cost key; 16-way
//    deal equalizes warp sums (LPT).
// images: [8,128,56,56] f32, rois: [512,4] f32, roi_idx: [512] i32,
// out: [512,128,7,7] f32.

#define OUT_D 7
#define ROWH4    16                 // H4 (8-byte) units per plane row (64 halves)
#define PLANE_H4 (56 * ROWH4)       // H4 units per (b,c) plane

// fp16 planes: 1024 planes x 56 rows x 64 halves (+pad for q=15 overread)
__device__ __align__(16) unsigned long long g_plane[1024 * PLANE_H4 + 32];

__device__ int        g_meta[512];  // roi | cp0q<<16 | narrow<<24
__device__ ulonglong2 g_ybin[512];  // {ysP, nP}: byte i = ys / row-count of y-bin i
__device__ ulonglong2 g_xbin[512];  // {xsP, xeP}: byte j = half-index bounds (frac3-based)
__device__ int        g_start[9];   // per-image segment starts

// ---- fp32 -> fp16 padded plane conversion (once per launch) ----
__global__ void convert_kernel(const float* __restrict__ images)
{
    const int j = blockIdx.x * 256 + threadIdx.x;   // 802816 float4 total
    float4 v = reinterpret_cast<const float4*>(images)[j];
    const int r  = j / 14;                          // global row = plane*56 + y
    const int c4 = j - r * 14;
    __half2 lo = __floats2half2_rn(v.x, v.y);
    __half2 hi = __floats2half2_rn(v.z, v.w);
    uint2 w;
    w.x = *reinterpret_cast<unsigned*>(&lo);
    w.y = *reinterpret_cast<unsigned*>(&hi);
    reinterpret_cast<uint2*>(g_plane)[r * ROWH4 + c4] = w;
}

// ---- per-ROI geometry + image bucketing + descending cost sort ----
__global__ void prep_kernel(const float* __restrict__ rois,
                            const int*   __restrict__ roi_idx)
{
    __shared__ int cnt[8];
    __shared__ int base[8];
    __shared__ int hist[8][128];
    const int tid = threadIdx.x;          // 512 threads, one block
    if (tid < 8) cnt[tid] = 0;
    for (int i = tid; i < 8 * 128; i += 512) (&hist[0][0])[i] = 0;
    __syncthreads();
    const int img = roi_idx[tid];
    atomicAdd(&cnt[img], 1);
    __syncthreads();
    if (tid == 0) {
        int acc = 0;
        for (int i = 0; i < 8; i++) { base[i] = acc; g_start[i] = acc; acc += cnt[i]; }
        g_start[8] = acc;
    }
    __syncthreads();

    const float4 box = reinterpret_cast<const float4*>(rois)[tid];
    // Match jnp: fp32 floor/ceil then int cast.
    const int x1 = (int)floorf(box.x * 56.0f);
    const int y1 = (int)floorf(box.y * 56.0f);
    const int x2 = (int)ceilf (box.z * 56.0f);
    const int y2 = (int)ceilf (box.w * 56.0f);
    const int Lx = x2 - x1, Ly = y2 - y1;
    const int frac3 = x1 & 3;             // offset from 4-half-aligned base
    const int cp0q  = x1 >> 2;            // H4-unit base within row (<= 6)

    unsigned long long ysP = 0, nP = 0, xsP = 0, xeP = 0;
    for (int j = 0; j < OUT_D; j++) {
        const int ys = y1 + (j * Ly) / 7;
        const int ye = y1 + ((j + 1) * Ly + 6) / 7;     // ceil div, ye > ys
        ysP |= (unsigned long long)ys << (8 * j);
        nP  |= (unsigned long long)(ye - ys) << (8 * j);
        const int xs = (j * Lx) / 7 + frac3;            // half-index in colmax
        const int xe = ((j + 1) * Lx + 6) / 7 + frac3;  // <= 59 < 64
        xsP |= (unsigned long long)xs << (8 * j);
        xeP |= (unsigned long long)xe << (8 * j);
    }
    const int narrow = (frac3 + Lx) <= 32;
    // cost key: rows, wides cost ~2x narrows -> bias them first. key < 128.
    const int key = Ly + (narrow ? 0 : 57);

    atomicAdd(&hist[img][key], 1);
    __syncthreads();
    if (tid < 8) {                        // descending prefix (big keys first)
        int off = 0;
        for (int v = 127; v >= 0; v--) { int t = hist[tid][v]; hist[tid][v] = off; off += t; }
    }
    __syncthreads();
    const int pos = base[img] + atomicAdd(&hist[img][key], 1);
    g_meta[pos] = tid | (cp0q << 16) | (narrow << 24);
    g_ybin[pos] = make_ulonglong2(ysP, nP);
    g_xbin[pos] = make_ulonglong2(xsP, xeP);
}

__device__ __forceinline__ int bget(unsigned long long p, int i) {
    return (int)((p >> (8 * i)) & 0xFF);
}

struct H4 { __half2 a, b; };

__device__ __forceinline__ H4 ldh4(const uint2* p) {
    uint2 t = __ldg(p);
    H4 h;
    h.a = *reinterpret_cast<__half2*>(&t.x);
    h.b = *reinterpret_cast<__half2*>(&t.y);
    return h;
}
__device__ __forceinline__ H4 h4max(H4 x, H4 y) {
    x.a = __hmax2(x.a, y.a);
    x.b = __hmax2(x.b, y.b);
    return x;
}
__device__ __forceinline__ unsigned h2u(__half2 v) { return *reinterpret_cast<unsigned*>(&v); }
__device__ __forceinline__ __half2 u2h(unsigned v) { return *reinterpret_cast<__half2*>(&v); }

__global__ __launch_bounds__(256, 7)
void roipool_kernel(float* __restrict__ out)
{
    // colmax scratch only; no SMEM plane. ch1 block at +16-word offset.
    __shared__ __align__(16) __half2 colmaxA[2 * 8 * OUT_D * 32 + 16];   // 14400 B

    const int bid  = blockIdx.x;          // ((b*64 + cp) << 1) | half
    const int half = bid & 1;
    const int bc   = bid >> 1;
    const int b    = bc >> 6;
    const int c0   = (bc & 63) * 2;

    const int tid  = threadIdx.x;
    const int warp = tid >> 5;
    const int lane = tid & 31;

    const uint2* pl = reinterpret_cast<const uint2*>(g_plane)
                      + (size_t)(b * 128 + c0) * PLANE_H4;

    __half2* cmw  = colmaxA + warp * (OUT_D * 32);
    __half2* cmw1 = colmaxA + 8 * (OUT_D * 32) + 16 + warp * (OUT_D * 32);

    const int s = g_start[b];
    const int e = g_start[b + 1];

    // 16-way deal over the descending-sorted segment (LPT balance).
    for (int k = s + warp * 2 + half; k < e; k += 16) {
        const int meta = g_meta[k];
        const ulonglong2 yb = g_ybin[k];
        const int cp0q   = (meta >> 16) & 0xFF;
        const int narrow =  meta >> 24;

        if (narrow) {
            // quarter-warps: q = H4 column, p = row parity, ch = channel
            const int q  = lane & 7;
            const int p  = (lane >> 3) & 1;
            const int ch = lane >> 4;
            const uint2* baseq = pl + ch * PLANE_H4 + cp0q + q;
            __half2* cmc = ch ? cmw1 : cmw;
            #pragma unroll
            for (int i = 0; i < OUT_D; i++) {
                const int ys = bget(yb.x, i);
                const int n  = bget(yb.y, i);
                const int np = (n + 1 - p) >> 1;          // parity-p row count
                const int r0 = np ? (ys + p) : ys;        // np==0: re-read ys
                const uint2* ptr = baseq + r0 * ROWH4;
                H4 m = ldh4(ptr);
                int rem = np ? (np - 1) : 0;
                ptr += 2 * ROWH4;
                while (rem >= 2) {                        // unroll 2 (4 rows)
                    m = h4max(h4max(m, ldh4(ptr)), ldh4(ptr + 2 * ROWH4));
                    ptr += 4 * ROWH4;
                    rem -= 2;
                }
                if (rem) m = h4max(m, ldh4(ptr));
                // merge the two row parities
                const unsigned ax = __shfl_xor_sync(0xFFFFFFFFu, h2u(m.a), 8);
                const unsigned bx = __shfl_xor_sync(0xFFFFFFFFu, h2u(m.b), 8);
                m.a = __hmax2(m.a, u2h(ax));
                m.b = __hmax2(m.b, u2h(bx));
                if (p == 0) {
                    cmc[i * 32 + 2 * q]     = m.a;
                    cmc[i * 32 + 2 * q + 1] = m.b;
                }
            }
        } else {
            // 16 lanes per channel cover 64 halves, 1 row per LDG.64.
            const int q  = lane & 15;
            const int ch = lane >> 4;
            const uint2* baseq = pl + ch * PLANE_H4 + cp0q + q;
            __half2* cmc = ch ? cmw1 : cmw;
            #pragma unroll
            for (int i = 0; i < OUT_D; i++) {
                const int ys = bget(yb.x, i);
                const int n  = bget(yb.y, i);
                const uint2* ptr = baseq + ys * ROWH4;
                H4 m = ldh4(ptr);                         // peel (bin non-empty)
                int rem = n - 1;
                ptr += ROWH4;
                while (rem >= 2) {                        // unroll 2
                    m = h4max(h4max(m, ldh4(ptr)), ldh4(ptr + ROWH4));
                    ptr += 2 * ROWH4;
                    rem -= 2;
                }
                if (rem) m = h4max(m, ldh4(ptr));
                cmc[i * 32 + 2 * q]     = m.a;
                cmc[i * 32 + 2 * q + 1] = m.b;
            }
        }
        __syncwarp();

        // ---- Pass 2: 49 outputs x 2 channels; shared index math ----
        const ulonglong2 xb = g_xbin[k];
        const int r = meta & 0xFFFF;
        float* outr = out + ((size_t)r * 128 + c0) * (OUT_D * OUT_D);
        #pragma unroll
        for (int bs = 0; bs < 64; bs += 32) {
            const int o = bs + lane;
            if (o < OUT_D * OUT_D) {
                const int i  = (o * 37) >> 8;             // o/7 for o<49
                const int j  = o - i * 7;
                const int xs = bget(xb.x, j);
                const int xe = bget(xb.y, j);
                const __half* cA = reinterpret_cast<const __half*>(cmw  + i * 32);
                const __half* cB = reinterpret_cast<const __half*>(cmw1 + i * 32);
                __half m0 = cA[xs];
                __half m1 = cB[xs];
                for (int x = xs + 1; x < xe; x++) {
                    m0 = __hmax(m0, cA[x]);
                    m1 = __hmax(m1, cB[x]);
                }
                outr[o]                 = __half2float(m0);
                outr[o + OUT_D * OUT_D] = __half2float(m1);
            }
        }
        __syncwarp();   // protect colmax before next ROI's pass 1
    }
}

extern "C" void kernel_launch(void* const* d_in, const int* in_sizes, int n_in,
                              void* d_out, int out_size)
{
    const float* images  = (const float*)d_in[0];   // [8,128,56,56]
    const float* rois    = (const float*)d_in[1];   // [512,4]
    const int*   roi_idx = (const int*)  d_in[2];   // [512]
    float*       out     = (float*)d_out;           // [512,128,7,7]

    // 8*128*3136 floats / 4 = 802816 float4 = 3136 blocks x 256 threads
    convert_kernel<<<3136, 256>>>(images);
    prep_kernel<<<1, 512>>>(rois, roi_idx);
    roipool_kernel<<<8 * 64 * 2, 256>>>(out);
}